// round 1
// baseline (speedup 1.0000x reference)
#include <cuda_runtime.h>
#include <cstdint>
#include <math.h>

// ---------------------------------------------------------------------------
// SelectiveSSM: B=4, L=1024, D_MODEL=64, D_STATE=128, D_INNER=128
// Pipeline:
//   K0: weight transposes + w_pool = mean_i W_in[i,:]
//   K1: projections (gate, delta=softplus, Bm+bias, Cm+bias) + x_pool
//   K2: Abar[row][s] = mean_i exp(delta_i * A[i,s])   (MUFU-bound)
//   K3a: chunked scan (64 blocks): local h, cumA, c*cumA, warp-reduced y_loc,
//        chunk summaries (P, Q)
//   K3b: chunk-prefix scan (1 block): H at chunk starts
//   K4: y = y_loc + <c*cumA, H>, silu gate, W_out GEMV, residual, LayerNorm
// ---------------------------------------------------------------------------

#define NB    4
#define NL    1024
#define NROW  4096          // NB*NL
#define DM    64
#define DS    128
#define DI    128
#define NCH   16            // chunks per batch
#define TC    64            // timesteps per chunk
#define R1    28            // rows per block, K1
#define R2    16            // rows per block, K2
#define R4    16            // rows per block, K4

// scratch (device globals: allocation-free)
__device__ float g_WT[64 * 512];      // transposed [d][f] for features 128..639
__device__ float g_WT2[128 * 64];     // W_out transposed [i][d]
__device__ float g_wpool[64];
__device__ float g_gate [NROW * DI];
__device__ float g_delta[NROW * DI];
__device__ float g_bm   [NROW * DS];  // Bm + b_B
__device__ float g_c    [NROW * DS];  // Cm + b_C
__device__ float g_pool [NROW];
__device__ float g_a    [NROW * DS];  // Abar
__device__ float g_cc   [NROW * DS];  // c * cumA
__device__ float g_yloc [NROW];
__device__ float g_P    [NB * NCH * DS];
__device__ float g_Q    [NB * NCH * DS];
__device__ float g_H    [NB * NCH * DS];

__device__ __forceinline__ float ex2f(float v) {
    float r;
    asm("ex2.approx.ftz.f32 %0, %1;" : "=f"(r) : "f"(v));
    return r;
}

// ---------------------------------------------------------------------------
// K0: build transposed weights + pooled W_in column means
// ---------------------------------------------------------------------------
__global__ void k0(const float* __restrict__ Win, const float* __restrict__ Wd,
                   const float* __restrict__ WB,  const float* __restrict__ WC,
                   const float* __restrict__ Wout) {
    int idx = blockIdx.x * blockDim.x + threadIdx.x;
    int stride = gridDim.x * blockDim.x;
    // WT[d*512 + f], feature = 128 + f
    for (int i = idx; i < 64 * 512; i += stride) {
        int d = i >> 9, f = i & 511;
        float v;
        if (f < 128)      v = Win[(128 + f) * 64 + d];   // gate rows of W_in
        else if (f < 256) v = Wd [(f - 128) * 64 + d];
        else if (f < 384) v = WB [(f - 256) * 64 + d];
        else              v = WC [(f - 384) * 64 + d];
        g_WT[i] = v;
    }
    // WT2[i*64 + d] = W_out[d*128 + i]
    for (int i = idx; i < 128 * 64; i += stride) {
        int ii = i >> 6, d = i & 63;
        g_WT2[i] = Wout[d * 128 + ii];
    }
    if (idx < 64) {
        float s = 0.f;
        for (int i = 0; i < 128; i++) s += Win[i * 64 + idx];
        g_wpool[idx] = s * (1.0f / 128.0f);
    }
}

// ---------------------------------------------------------------------------
// K1: projections. 512 threads: f=tid -> feature 128+f
//   mode 0: gate, 1: delta (softplus+bias), 2: Bm+bias, 3: Cm+bias
// ---------------------------------------------------------------------------
__global__ __launch_bounds__(512, 1) void k1(const float* __restrict__ x,
                                             const float* __restrict__ bd,
                                             const float* __restrict__ bB,
                                             const float* __restrict__ bC) {
    __shared__ float xs[R1 * 64];
    int row0 = blockIdx.x * R1;
    int nr = NROW - row0; if (nr > R1) nr = R1;
    int tid = threadIdx.x;
    for (int i = tid; i < nr * 64; i += 512) xs[i] = x[row0 * 64 + i];
    __syncthreads();

    float w[64];
#pragma unroll
    for (int d = 0; d < 64; d++) w[d] = g_WT[d * 512 + tid];

    int mode = tid >> 7;
    int fo = tid & 127;
    float bias = 0.f;
    if (mode == 1) bias = bd[fo];
    else if (mode == 2) bias = bB[fo];
    else if (mode == 3) bias = bC[fo];

    for (int r = 0; r < nr; r++) {
        float a0 = 0.f, a1 = 0.f;
#pragma unroll
        for (int d = 0; d < 64; d += 2) {
            a0 = fmaf(w[d],     xs[r * 64 + d],     a0);
            a1 = fmaf(w[d + 1], xs[r * 64 + d + 1], a1);
        }
        float acc = a0 + a1 + bias;
        int o = (row0 + r) * 128 + fo;
        if (mode == 0)      g_gate[o]  = acc;
        else if (mode == 1) g_delta[o] = log1pf(expf(acc));   // softplus
        else if (mode == 2) g_bm[o]    = acc;
        else                g_c[o]     = acc;
    }

    // x_pool for this block's rows (thread r handles row r)
    if (tid < nr) {
        float p = 0.f;
#pragma unroll
        for (int d = 0; d < 64; d++) p = fmaf(g_wpool[d], xs[tid * 64 + d], p);
        g_pool[row0 + tid] = p;
    }
}

// ---------------------------------------------------------------------------
// K2: Abar[row][s] = (1/128) * sum_i exp(delta[row][i] * A[i][s])
//   A pre-scaled by log2(e) in smem -> FMUL + MUFU.EX2 + FADD per term.
// ---------------------------------------------------------------------------
__global__ __launch_bounds__(512) void k2(const float* __restrict__ A) {
    extern __shared__ float sm[];
    float* Asm = sm;              // 128*128, scaled
    float* dsm = sm + 128 * 128;  // 16*128
    int tid = threadIdx.x;
    int row0 = blockIdx.x * R2;
    for (int i = tid; i < 128 * 128; i += 512) Asm[i] = A[i] * 1.4426950408889634f;
    for (int i = tid; i < R2 * 128; i += 512) dsm[i] = g_delta[row0 * 128 + i];
    __syncthreads();

    int s = tid & 127, rs = tid >> 7;
    for (int k = 0; k < 4; k++) {
        int r = rs * 4 + k;
        const float* dr = dsm + r * 128;
        float a0 = 0.f, a1 = 0.f, a2 = 0.f, a3 = 0.f;
#pragma unroll
        for (int i = 0; i < 128; i += 4) {
            a0 += ex2f(dr[i]     * Asm[(i)     * 128 + s]);
            a1 += ex2f(dr[i + 1] * Asm[(i + 1) * 128 + s]);
            a2 += ex2f(dr[i + 2] * Asm[(i + 2) * 128 + s]);
            a3 += ex2f(dr[i + 3] * Asm[(i + 3) * 128 + s]);
        }
        g_a[(row0 + r) * 128 + s] = (a0 + a1 + a2 + a3) * (1.0f / 128.0f);
    }
}

// ---------------------------------------------------------------------------
// K3a: chunked scan. grid = NB*NCH blocks, 128 threads (thread = state s).
//   h_loc (h_in=0), cumA = prod a, stores c*cumA, warp-reduced y_loc,
//   chunk summary P=cumA_end, Q=h_loc_end.
// ---------------------------------------------------------------------------
__global__ __launch_bounds__(128) void k3a() {
    int b = blockIdx.x >> 4, g = blockIdx.x & 15;
    int s = threadIdx.x, lane = s & 31, warp = s >> 5;
    __shared__ float wp[4 * TC];
    int rbase = b * NL + g * TC;
    int base = rbase * 128;

    float h = 0.f, cA = 1.f;
    float a8[2][8], b8[2][8], c8[2][8], p8[2][8];
#pragma unroll
    for (int j = 0; j < 8; j++) {
        int off = base + j * 128 + s;
        a8[0][j] = g_a[off]; b8[0][j] = g_bm[off]; c8[0][j] = g_c[off];
        p8[0][j] = g_pool[rbase + j];
    }
    for (int T = 0; T < 8; T++) {
        int cur = T & 1, nxt = cur ^ 1;
        if (T < 7) {
#pragma unroll
            for (int j = 0; j < 8; j++) {
                int t = (T + 1) * 8 + j;
                int off = base + t * 128 + s;
                a8[nxt][j] = g_a[off]; b8[nxt][j] = g_bm[off]; c8[nxt][j] = g_c[off];
                p8[nxt][j] = g_pool[rbase + t];
            }
        }
#pragma unroll
        for (int j = 0; j < 8; j++) {
            int t = T * 8 + j;
            float a = a8[cur][j];
            h = fmaf(a, h, b8[cur][j] * p8[cur][j]);  // bx = Bm * x_pool
            cA *= a;
            g_cc[base + t * 128 + s] = c8[cur][j] * cA;
            float p = c8[cur][j] * h;
            p += __shfl_down_sync(0xffffffffu, p, 16);
            p += __shfl_down_sync(0xffffffffu, p, 8);
            p += __shfl_down_sync(0xffffffffu, p, 4);
            p += __shfl_down_sync(0xffffffffu, p, 2);
            p += __shfl_down_sync(0xffffffffu, p, 1);
            if (lane == 0) wp[warp * TC + t] = p;
        }
    }
    int ps = (b * NCH + g) * 128 + s;
    g_P[ps] = cA;
    g_Q[ps] = h;
    __syncthreads();
    if (s < TC)
        g_yloc[rbase + s] = wp[s] + wp[TC + s] + wp[2 * TC + s] + wp[3 * TC + s];
}

// ---------------------------------------------------------------------------
// K3b: chunk-prefix. 1 block, 512 threads: (b = tid>>7, s = tid&127)
// ---------------------------------------------------------------------------
__global__ void k3b() {
    int tid = threadIdx.x;
    int b = tid >> 7, s = tid & 127;
    float P[NCH], Q[NCH];
#pragma unroll
    for (int g = 0; g < NCH; g++) {
        int o = (b * NCH + g) * 128 + s;
        P[g] = g_P[o]; Q[g] = g_Q[o];
    }
    float H = 0.f;
#pragma unroll
    for (int g = 0; g < NCH; g++) {
        g_H[(b * NCH + g) * 128 + s] = H;
        H = fmaf(P[g], H, Q[g]);
    }
}

// ---------------------------------------------------------------------------
// K4: y = yloc + <cc, H>; yi = y*silu(gate); out = yi @ W_out^T + x; LayerNorm.
//   grid 256 blocks x 16 rows, 256 threads.
// ---------------------------------------------------------------------------
__global__ __launch_bounds__(256) void k4(const float* __restrict__ x,
                                          const float* __restrict__ lnw,
                                          const float* __restrict__ lnb,
                                          float* __restrict__ out) {
    __shared__ float WT2s[128 * 64];
    __shared__ float yis[R4 * 128];
    __shared__ float Hs[128];
    __shared__ float red[8];
    __shared__ float ys[R4];
    __shared__ float lred[8][2];
    int tid = threadIdx.x;
    int row0 = blockIdx.x * R4;
    int b = row0 >> 10;
    int g = (row0 & 1023) >> 6;   // all 16 rows share one chunk (16 | 64)
    for (int i = tid; i < 128 * 64; i += 256) WT2s[i] = g_WT2[i];
    if (tid < 128) Hs[tid] = g_H[(b * NCH + g) * 128 + tid];
    __syncthreads();

    // Phase A: per pair of rows, reduce y and build yi = y*silu(gate)
    int s = tid & 127, rr = tid >> 7;
    for (int pr = 0; pr < 8; pr++) {
        int r = pr * 2 + rr;
        int row = row0 + r;
        float gt = g_gate[row * 128 + s];
        float p = g_cc[row * 128 + s] * Hs[s];
        p += __shfl_down_sync(0xffffffffu, p, 16);
        p += __shfl_down_sync(0xffffffffu, p, 8);
        p += __shfl_down_sync(0xffffffffu, p, 4);
        p += __shfl_down_sync(0xffffffffu, p, 2);
        p += __shfl_down_sync(0xffffffffu, p, 1);
        if ((tid & 31) == 0) red[tid >> 5] = p;
        __syncthreads();
        if (tid == 0)
            ys[pr * 2]     = g_yloc[row0 + pr * 2]     + red[0] + red[1] + red[2] + red[3];
        if (tid == 128)
            ys[pr * 2 + 1] = g_yloc[row0 + pr * 2 + 1] + red[4] + red[5] + red[6] + red[7];
        __syncthreads();
        float y = ys[r];
        float sig = 1.0f / (1.0f + __expf(-gt));
        yis[r * 128 + s] = y * gt * sig;
    }
    __syncthreads();

    // Phase B: out_d = sum_i WT2[i][d]*yi[r][i]; residual; LayerNorm over 64.
    int d = tid & 63, sub = tid >> 6;
    for (int q = 0; q < 4; q++) {
        int r = q * 4 + sub;
        int row = row0 + r;
        float acc = 0.f;
#pragma unroll
        for (int i = 0; i < 128; i++)
            acc = fmaf(WT2s[i * 64 + d], yis[r * 128 + i], acc);
        float v = acc + x[row * 64 + d];
        float sv = v, sq = v * v;
#pragma unroll
        for (int o = 16; o > 0; o >>= 1) {
            sv += __shfl_down_sync(0xffffffffu, sv, o);
            sq += __shfl_down_sync(0xffffffffu, sq, o);
        }
        int w2 = tid >> 5;
        if ((tid & 31) == 0) { lred[w2][0] = sv; lred[w2][1] = sq; }
        __syncthreads();
        float S  = lred[sub * 2][0] + lred[sub * 2 + 1][0];
        float SS = lred[sub * 2][1] + lred[sub * 2 + 1][1];
        float mu = S * (1.0f / 64.0f);
        float var = SS * (1.0f / 64.0f) - mu * mu;
        out[row * 64 + d] = (v - mu) * rsqrtf(var + 1e-5f) * lnw[d] + lnb[d];
        __syncthreads();
    }
}

// ---------------------------------------------------------------------------
extern "C" void kernel_launch(void* const* d_in, const int* in_sizes, int n_in,
                              void* d_out, int out_size) {
    const float* x    = (const float*)d_in[0];
    const float* Win  = (const float*)d_in[1];
    const float* Wd   = (const float*)d_in[2];
    const float* bd   = (const float*)d_in[3];
    const float* WB   = (const float*)d_in[4];
    const float* bB   = (const float*)d_in[5];
    const float* WC   = (const float*)d_in[6];
    const float* bC   = (const float*)d_in[7];
    const float* A    = (const float*)d_in[8];
    const float* Wout = (const float*)d_in[9];
    const float* lnw  = (const float*)d_in[10];
    const float* lnb  = (const float*)d_in[11];
    float* out = (float*)d_out;

    cudaFuncSetAttribute(k2, cudaFuncAttributeMaxDynamicSharedMemorySize,
                         (128 * 128 + R2 * 128) * (int)sizeof(float));

    k0<<<64, 256>>>(Win, Wd, WB, WC, Wout);
    k1<<<(NROW + R1 - 1) / R1, 512>>>(x, bd, bB, bC);
    k2<<<NROW / R2, 512, (128 * 128 + R2 * 128) * sizeof(float)>>>(A);
    k3a<<<NB * NCH, 128>>>();
    k3b<<<1, 512>>>();
    k4<<<NROW / R4, 256>>>(x, lnw, lnb, out);
}

// round 2
// speedup vs baseline: 1.1212x; 1.1212x over previous
#include <cuda_runtime.h>
#include <cstdint>
#include <math.h>

// ---------------------------------------------------------------------------
// SelectiveSSM: B=4, L=1024, D_MODEL=64, D_STATE=128, D_INNER=128
//   K0: weight transposes + w_pool
//   K1: projections (gate, delta=softplus, Bm+bias, Cm+bias) + x_pool
//   K2: Abar[row][s] = mean_i exp(delta_i * A[i,s])   (MUFU-bound)
//   K3a: chunked scan, TC=16: h_loc, cumA -> stores c*cumA and c*h_loc
//   K3b: chunk-prefix scan (1 block)
//   K4: y = sum_s(ch + cc*H), silu gate, W_out GEMV, residual, LayerNorm
// ---------------------------------------------------------------------------

#define NB    4
#define NL    1024
#define NROW  4096
#define DM    64
#define DS    128
#define DI    128
#define NCH   64            // chunks per batch
#define TC    16            // timesteps per chunk
#define R1    28            // rows per block, K1
#define R2    16            // rows per block, K2
#define R4    16            // rows per block, K4 ( == TC )

__device__ float g_WT[64 * 512];
__device__ float g_WT2[128 * 64];
__device__ float g_wpool[64];
__device__ float g_gate [NROW * DI];
__device__ float g_delta[NROW * DI];
__device__ float g_bm   [NROW * DS];
__device__ float g_c    [NROW * DS];
__device__ float g_pool [NROW];
__device__ float g_a    [NROW * DS];
__device__ float g_cc   [NROW * DS];   // c * cumA
__device__ float g_ch   [NROW * DS];   // c * h_loc
__device__ float g_P    [NB * NCH * DS];
__device__ float g_Q    [NB * NCH * DS];
__device__ float g_H    [NB * NCH * DS];

__device__ __forceinline__ float ex2f(float v) {
    float r;
    asm("ex2.approx.ftz.f32 %0, %1;" : "=f"(r) : "f"(v));
    return r;
}

// ---------------------------------------------------------------------------
__global__ void k0(const float* __restrict__ Win, const float* __restrict__ Wd,
                   const float* __restrict__ WB,  const float* __restrict__ WC,
                   const float* __restrict__ Wout) {
    int idx = blockIdx.x * blockDim.x + threadIdx.x;
    int stride = gridDim.x * blockDim.x;
    for (int i = idx; i < 64 * 512; i += stride) {
        int d = i >> 9, f = i & 511;
        float v;
        if (f < 128)      v = Win[(128 + f) * 64 + d];
        else if (f < 256) v = Wd [(f - 128) * 64 + d];
        else if (f < 384) v = WB [(f - 256) * 64 + d];
        else              v = WC [(f - 384) * 64 + d];
        g_WT[i] = v;
    }
    for (int i = idx; i < 128 * 64; i += stride) {
        int ii = i >> 6, d = i & 63;
        g_WT2[i] = Wout[d * 128 + ii];
    }
    if (idx < 64) {
        float s = 0.f;
        for (int i = 0; i < 128; i++) s += Win[i * 64 + idx];
        g_wpool[idx] = s * (1.0f / 128.0f);
    }
}

// ---------------------------------------------------------------------------
__global__ __launch_bounds__(512, 1) void k1(const float* __restrict__ x,
                                             const float* __restrict__ bd,
                                             const float* __restrict__ bB,
                                             const float* __restrict__ bC) {
    __shared__ float xs[R1 * 64];
    int row0 = blockIdx.x * R1;
    int nr = NROW - row0; if (nr > R1) nr = R1;
    int tid = threadIdx.x;
    for (int i = tid; i < nr * 64; i += 512) xs[i] = x[row0 * 64 + i];
    __syncthreads();

    float w[64];
#pragma unroll
    for (int d = 0; d < 64; d++) w[d] = g_WT[d * 512 + tid];

    int mode = tid >> 7;
    int fo = tid & 127;
    float bias = 0.f;
    if (mode == 1) bias = bd[fo];
    else if (mode == 2) bias = bB[fo];
    else if (mode == 3) bias = bC[fo];

    for (int r = 0; r < nr; r++) {
        const float4* xs4 = (const float4*)(xs + r * 64);
        float a0 = 0.f, a1 = 0.f, a2 = 0.f, a3 = 0.f;
#pragma unroll
        for (int d4 = 0; d4 < 16; d4++) {
            float4 xv = xs4[d4];
            a0 = fmaf(w[4 * d4],     xv.x, a0);
            a1 = fmaf(w[4 * d4 + 1], xv.y, a1);
            a2 = fmaf(w[4 * d4 + 2], xv.z, a2);
            a3 = fmaf(w[4 * d4 + 3], xv.w, a3);
        }
        float acc = (a0 + a1) + (a2 + a3) + bias;
        int o = (row0 + r) * 128 + fo;
        if (mode == 0)      g_gate[o]  = acc;
        else if (mode == 1) g_delta[o] = log1pf(expf(acc));
        else if (mode == 2) g_bm[o]    = acc;
        else                g_c[o]     = acc;
    }

    if (tid < nr) {
        float p = 0.f;
#pragma unroll
        for (int d = 0; d < 64; d++) p = fmaf(g_wpool[d], xs[tid * 64 + d], p);
        g_pool[row0 + tid] = p;
    }
}

// ---------------------------------------------------------------------------
__global__ __launch_bounds__(512) void k2(const float* __restrict__ A) {
    extern __shared__ float sm[];
    float* Asm = sm;
    float* dsm = sm + 128 * 128;
    int tid = threadIdx.x;
    int row0 = blockIdx.x * R2;
    for (int i = tid; i < 128 * 128; i += 512) Asm[i] = A[i] * 1.4426950408889634f;
    for (int i = tid; i < R2 * 128; i += 512) dsm[i] = g_delta[row0 * 128 + i];
    __syncthreads();

    int s = tid & 127, rs = tid >> 7;
    for (int k = 0; k < 4; k++) {
        int r = rs * 4 + k;
        const float* dr = dsm + r * 128;
        float a0 = 0.f, a1 = 0.f, a2 = 0.f, a3 = 0.f;
#pragma unroll
        for (int i = 0; i < 128; i += 4) {
            a0 += ex2f(dr[i]     * Asm[(i)     * 128 + s]);
            a1 += ex2f(dr[i + 1] * Asm[(i + 1) * 128 + s]);
            a2 += ex2f(dr[i + 2] * Asm[(i + 2) * 128 + s]);
            a3 += ex2f(dr[i + 3] * Asm[(i + 3) * 128 + s]);
        }
        g_a[(row0 + r) * 128 + s] = (a0 + a1 + a2 + a3) * (1.0f / 128.0f);
    }
}

// ---------------------------------------------------------------------------
// K3a: 256 blocks x 128 threads. Prefetch all 16 steps (MLP=48), then a
//      pure-FMA serial recurrence (4-cyc chain per step). No shuffles.
// ---------------------------------------------------------------------------
__global__ __launch_bounds__(128) void k3a() {
    int b = blockIdx.x >> 6, g = blockIdx.x & 63;
    int s = threadIdx.x;
    int rbase = b * NL + g * TC;
    int base = rbase * 128;

    float a[TC], bm[TC], c[TC], p[TC];
#pragma unroll
    for (int t = 0; t < TC; t++) {
        int off = base + t * 128 + s;
        a[t]  = g_a[off];
        bm[t] = g_bm[off];
        c[t]  = g_c[off];
    }
#pragma unroll
    for (int t = 0; t < TC; t++) p[t] = g_pool[rbase + t];

    float h = 0.f, cA = 1.f;
#pragma unroll
    for (int t = 0; t < TC; t++) {
        h = fmaf(a[t], h, bm[t] * p[t]);
        cA *= a[t];
        int off = base + t * 128 + s;
        g_cc[off] = c[t] * cA;
        g_ch[off] = c[t] * h;
    }
    int ps = (b * NCH + g) * 128 + s;
    g_P[ps] = cA;
    g_Q[ps] = h;
}

// ---------------------------------------------------------------------------
// K3b: 1 block, 512 threads, (b = tid>>7, s = tid&127), 64-chunk serial scan
//      with 8-deep double-buffered prefetch.
// ---------------------------------------------------------------------------
__global__ void k3b() {
    int tid = threadIdx.x;
    int b = tid >> 7, s = tid & 127;
    int o0 = b * NCH * 128 + s;
    float P[2][8], Q[2][8];
#pragma unroll
    for (int j = 0; j < 8; j++) {
        P[0][j] = g_P[o0 + j * 128];
        Q[0][j] = g_Q[o0 + j * 128];
    }
    float H = 0.f;
    for (int T = 0; T < 8; T++) {
        int cur = T & 1, nxt = cur ^ 1;
        if (T < 7) {
#pragma unroll
            for (int j = 0; j < 8; j++) {
                int o = o0 + ((T + 1) * 8 + j) * 128;
                P[nxt][j] = g_P[o];
                Q[nxt][j] = g_Q[o];
            }
        }
#pragma unroll
        for (int j = 0; j < 8; j++) {
            g_H[o0 + (T * 8 + j) * 128] = H;
            H = fmaf(P[cur][j], H, Q[cur][j]);
        }
    }
}

// ---------------------------------------------------------------------------
// K4: per block 16 rows (one chunk). Phase A: warp per 2 rows, butterfly
//     reduction of y = sum_s(ch + cc*H), build yi = y*silu(gate). Phase B:
//     W_out GEMV + residual + warp-private LayerNorm (lane owns d, d+32).
// ---------------------------------------------------------------------------
__global__ __launch_bounds__(256) void k4(const float* __restrict__ x,
                                          const float* __restrict__ lnw,
                                          const float* __restrict__ lnb,
                                          float* __restrict__ out) {
    __shared__ float WT2s[128 * 64];
    __shared__ float yis[R4 * 128];
    __shared__ float Hs[128];
    int tid = threadIdx.x, lane = tid & 31, w = tid >> 5;
    int row0 = blockIdx.x * R4;
    int b = row0 >> 10;
    int g = (row0 & 1023) >> 4;           // TC = 16
    for (int i = tid; i < 128 * 64; i += 256) WT2s[i] = g_WT2[i];
    if (tid < 128) Hs[tid] = g_H[(b * NCH + g) * 128 + tid];
    __syncthreads();

    // Phase A
#pragma unroll
    for (int rr = 0; rr < 2; rr++) {
        int r = w * 2 + rr;
        int row = row0 + r;
        float acc = 0.f;
        float gt[4];
#pragma unroll
        for (int q = 0; q < 4; q++) {
            int s = lane + q * 32;
            int off = row * 128 + s;
            acc += g_ch[off] + g_cc[off] * Hs[s];
            gt[q] = g_gate[off];
        }
#pragma unroll
        for (int o = 16; o > 0; o >>= 1) acc += __shfl_xor_sync(0xffffffffu, acc, o);
#pragma unroll
        for (int q = 0; q < 4; q++) {
            int s = lane + q * 32;
            float sig = 1.0f / (1.0f + __expf(-gt[q]));
            yis[r * 128 + s] = acc * gt[q] * sig;
        }
    }
    __syncthreads();

    // Phase B: warp w -> rows 2w, 2w+1; lane owns d = lane and lane+32
#pragma unroll
    for (int rr = 0; rr < 2; rr++) {
        int r = w * 2 + rr;
        int row = row0 + r;
        float acc0 = 0.f, acc1 = 0.f;
#pragma unroll
        for (int i = 0; i < 128; i++) {
            float yv = yis[r * 128 + i];
            acc0 = fmaf(WT2s[i * 64 + lane],      yv, acc0);
            acc1 = fmaf(WT2s[i * 64 + lane + 32], yv, acc1);
        }
        float v0 = acc0 + x[row * 64 + lane];
        float v1 = acc1 + x[row * 64 + lane + 32];
        float sv = v0 + v1, sq = v0 * v0 + v1 * v1;
#pragma unroll
        for (int o = 16; o > 0; o >>= 1) {
            sv += __shfl_xor_sync(0xffffffffu, sv, o);
            sq += __shfl_xor_sync(0xffffffffu, sq, o);
        }
        float mu  = sv * (1.0f / 64.0f);
        float var = sq * (1.0f / 64.0f) - mu * mu;
        float inv = rsqrtf(var + 1e-5f);
        out[row * 64 + lane]      = (v0 - mu) * inv * lnw[lane]      + lnb[lane];
        out[row * 64 + lane + 32] = (v1 - mu) * inv * lnw[lane + 32] + lnb[lane + 32];
    }
}

// ---------------------------------------------------------------------------
extern "C" void kernel_launch(void* const* d_in, const int* in_sizes, int n_in,
                              void* d_out, int out_size) {
    const float* x    = (const float*)d_in[0];
    const float* Win  = (const float*)d_in[1];
    const float* Wd   = (const float*)d_in[2];
    const float* bd   = (const float*)d_in[3];
    const float* WB   = (const float*)d_in[4];
    const float* bB   = (const float*)d_in[5];
    const float* WC   = (const float*)d_in[6];
    const float* bC   = (const float*)d_in[7];
    const float* A    = (const float*)d_in[8];
    const float* Wout = (const float*)d_in[9];
    const float* lnw  = (const float*)d_in[10];
    const float* lnb  = (const float*)d_in[11];
    float* out = (float*)d_out;

    cudaFuncSetAttribute(k2, cudaFuncAttributeMaxDynamicSharedMemorySize,
                         (128 * 128 + R2 * 128) * (int)sizeof(float));

    k0<<<64, 256>>>(Win, Wd, WB, WC, Wout);
    k1<<<(NROW + R1 - 1) / R1, 512>>>(x, bd, bB, bC);
    k2<<<NROW / R2, 512, (128 * 128 + R2 * 128) * sizeof(float)>>>(A);
    k3a<<<NB * NCH, 128>>>();
    k3b<<<1, 512>>>();
    k4<<<NROW / R4, 256>>>(x, lnw, lnb, out);
}

// round 3
// speedup vs baseline: 1.1929x; 1.0640x over previous
#include <cuda_runtime.h>
#include <cstdint>
#include <math.h>

// ---------------------------------------------------------------------------
// SelectiveSSM fused 2-kernel pipeline. B=4, L=1024, DM=64, DS=DI=128.
//   KA: per block = 16 rows = 1 chunk: projections (gate/delta/B/C) directly
//       from raw weights, x_pool (w_pool computed in-block), Abar (MUFU),
//       in-block chunk scan -> P,Q.  delta never leaves smem.
//   KC: per block = same chunk: chunk-prefix from P,Q (predicated),
//       local scan recompute, y reduction, silu gate, W_out GEMV,
//       residual + LayerNorm.
// ---------------------------------------------------------------------------

#define NB    4
#define NL    1024
#define NROW  4096
#define NCH   64            // chunks per batch
#define TC    16            // timesteps per chunk == rows per block
#define LOG2E 1.4426950408889634f

__device__ float g_gate [NROW * 128];
__device__ float g_bm   [NROW * 128];
__device__ float g_c    [NROW * 128];
__device__ float g_pool [NROW];
__device__ float g_a    [NROW * 128];
__device__ float g_P    [NB * NCH * 128];
__device__ float g_Q    [NB * NCH * 128];

__device__ __forceinline__ float ex2f(float v) {
    float r;
    asm("ex2.approx.ftz.f32 %0, %1;" : "=f"(r) : "f"(v));
    return r;
}

// ---------------------------------------------------------------------------
// KA: 256 blocks x 512 threads.  Dynamic smem layout (floats):
//   Asm[16384] | xs[1024] | dsm[2048] | bms[2048] | abars[2048] |
//   psum[512] | wpool[64] | pools[16]
// ---------------------------------------------------------------------------
#define KA_SMEM_FLOATS (16384 + 1024 + 2048 + 2048 + 2048 + 512 + 64 + 16)

__global__ __launch_bounds__(512) void ka(
    const float* __restrict__ x,   const float* __restrict__ Win,
    const float* __restrict__ Wd,  const float* __restrict__ bd,
    const float* __restrict__ WB,  const float* __restrict__ bB,
    const float* __restrict__ WC,  const float* __restrict__ bC,
    const float* __restrict__ A) {
    extern __shared__ float sm[];
    float* Asm   = sm;                 // 128*128, pre-scaled by log2(e)
    float* xs    = Asm + 16384;        // 16*64
    float* dsm   = xs + 1024;          // 16*128 delta
    float* bms   = dsm + 2048;         // 16*128 Bm
    float* abars = bms + 2048;         // 16*128 Abar
    float* psum  = abars + 2048;       // 8*64 wpool partials
    float* wpool = psum + 512;         // 64
    float* pools = wpool + 64;         // 16

    int tid = threadIdx.x;
    int row0 = blockIdx.x * TC;

    // phase 0: stage A (scaled), x rows, wpool partials
    for (int i = tid; i < 16384; i += 512) Asm[i] = A[i] * LOG2E;
    for (int i = tid; i < TC * 64; i += 512) xs[i] = x[row0 * 64 + i];
    {
        int d = tid & 63, part = tid >> 6;
        float s = 0.f;
        const float* p = Win + part * 16 * 64 + d;
#pragma unroll
        for (int i = 0; i < 16; i++) s += p[i * 64];
        psum[part * 64 + d] = s;
    }
    __syncthreads();

    if (tid < 64) {
        float s = 0.f;
#pragma unroll
        for (int p = 0; p < 8; p++) s += psum[p * 64 + tid];
        wpool[tid] = s * (1.0f / 128.0f);
    }

    // phase 1: projections. thread = one feature.
    int mode = tid >> 7, fo = tid & 127;
    const float* wrow;
    float bias = 0.f;
    if (mode == 0)      { wrow = Win + (128 + fo) * 64; }
    else if (mode == 1) { wrow = Wd + fo * 64; bias = bd[fo]; }
    else if (mode == 2) { wrow = WB + fo * 64; bias = bB[fo]; }
    else                { wrow = WC + fo * 64; bias = bC[fo]; }

    float w[64];
    const float4* wrow4 = (const float4*)wrow;
#pragma unroll
    for (int d4 = 0; d4 < 16; d4++) {
        float4 v = wrow4[d4];
        w[4 * d4] = v.x; w[4 * d4 + 1] = v.y; w[4 * d4 + 2] = v.z; w[4 * d4 + 3] = v.w;
    }

#pragma unroll 4
    for (int r = 0; r < TC; r++) {
        const float4* xs4 = (const float4*)(xs + r * 64);
        float a0 = 0.f, a1 = 0.f, a2 = 0.f, a3 = 0.f;
#pragma unroll
        for (int d4 = 0; d4 < 16; d4++) {
            float4 xv = xs4[d4];
            a0 = fmaf(w[4 * d4],     xv.x, a0);
            a1 = fmaf(w[4 * d4 + 1], xv.y, a1);
            a2 = fmaf(w[4 * d4 + 2], xv.z, a2);
            a3 = fmaf(w[4 * d4 + 3], xv.w, a3);
        }
        float acc = (a0 + a1) + (a2 + a3) + bias;
        int o = (row0 + r) * 128 + fo;
        if (mode == 0)      g_gate[o] = acc;
        else if (mode == 1) dsm[r * 128 + fo] = log1pf(expf(acc));  // softplus
        else if (mode == 2) { g_bm[o] = acc; bms[r * 128 + fo] = acc; }
        else                g_c[o] = acc;
    }
    __syncthreads();   // dsm, bms, wpool ready

    // phase 2a: x_pool (threads 0..15, then they join Abar)
    if (tid < TC) {
        float p = 0.f;
#pragma unroll
        for (int d = 0; d < 64; d++) p = fmaf(wpool[d], xs[tid * 64 + d], p);
        pools[tid] = p;
        g_pool[row0 + tid] = p;
    }

    // phase 2b: Abar. thread (s, rq) -> 4 rows.
    int s = tid & 127, rq = tid >> 7;
#pragma unroll
    for (int k = 0; k < 4; k++) {
        int r = rq * 4 + k;
        const float* dr = dsm + r * 128;
        float a0 = 0.f, a1 = 0.f, a2 = 0.f, a3 = 0.f;
#pragma unroll
        for (int i = 0; i < 128; i += 4) {
            a0 += ex2f(dr[i]     * Asm[(i)     * 128 + s]);
            a1 += ex2f(dr[i + 1] * Asm[(i + 1) * 128 + s]);
            a2 += ex2f(dr[i + 2] * Asm[(i + 2) * 128 + s]);
            a3 += ex2f(dr[i + 3] * Asm[(i + 3) * 128 + s]);
        }
        float v = ((a0 + a1) + (a2 + a3)) * (1.0f / 128.0f);
        g_a[(row0 + r) * 128 + s] = v;
        abars[r * 128 + s] = v;
    }
    __syncthreads();   // abars, pools ready

    // phase 3: in-block chunk scan -> P, Q   (chunk id == blockIdx.x)
    if (tid < 128) {
        float h = 0.f, cA = 1.f;
#pragma unroll
        for (int t = 0; t < TC; t++) {
            float a = abars[t * 128 + tid];
            h = fmaf(a, h, bms[t * 128 + tid] * pools[t]);
            cA *= a;
        }
        int ps = blockIdx.x * 128 + tid;
        g_P[ps] = cA;
        g_Q[ps] = h;
    }
}

// ---------------------------------------------------------------------------
// KC: 256 blocks x 256 threads. chunk-prefix + local scan + output.
// ---------------------------------------------------------------------------
__global__ __launch_bounds__(256) void kc(const float* __restrict__ x,
                                          const float* __restrict__ Wout,
                                          const float* __restrict__ lnw,
                                          const float* __restrict__ lnb,
                                          float* __restrict__ out) {
    __shared__ float WT2s[128 * 65];   // padded transpose of W_out
    __shared__ float vals[TC * 128];   // scan contribs, then reused as yi
    __shared__ float Hs[128];
    int tid = threadIdx.x, lane = tid & 31, w = tid >> 5;
    int row0 = blockIdx.x * TC;
    int g = blockIdx.x & 63;
    int b = blockIdx.x >> 6;

    // W_out transpose into padded smem (coalesced read, conflict-free write)
    for (int lin = tid; lin < 8192; lin += 256) {
        int d = lin >> 7, ii = lin & 127;
        WT2s[ii * 65 + d] = Wout[lin];
    }

    if (tid < 128) {
        int s = tid;
        // chunk prefix: H = scan over chunks gg < g (predicated, dbl-buffered)
        int o0 = (b * NCH) * 128 + s;
        float P[2][8], Q[2][8];
#pragma unroll
        for (int j = 0; j < 8; j++) {
            P[0][j] = g_P[o0 + j * 128];
            Q[0][j] = g_Q[o0 + j * 128];
        }
        float H = 0.f;
        for (int T = 0; T < 8; T++) {
            int cur = T & 1, nxt = cur ^ 1;
            if (T < 7) {
#pragma unroll
                for (int j = 0; j < 8; j++) {
                    int o = o0 + ((T + 1) * 8 + j) * 128;
                    P[nxt][j] = g_P[o];
                    Q[nxt][j] = g_Q[o];
                }
            }
#pragma unroll
            for (int j = 0; j < 8; j++) {
                int gg = T * 8 + j;
                if (gg < g) H = fmaf(P[cur][j], H, Q[cur][j]);
            }
        }
        Hs[s] = H;

        // local scan recompute; vals[t][s] = c*(h + cumA*H)
        float a[TC], bm[TC], c[TC], p[TC];
        int base = row0 * 128 + s;
#pragma unroll
        for (int t = 0; t < TC; t++) {
            a[t]  = g_a [base + t * 128];
            bm[t] = g_bm[base + t * 128];
            c[t]  = g_c [base + t * 128];
        }
#pragma unroll
        for (int t = 0; t < TC; t++) p[t] = g_pool[row0 + t];

        float h = 0.f, cA = 1.f;
#pragma unroll
        for (int t = 0; t < TC; t++) {
            h = fmaf(a[t], h, bm[t] * p[t]);
            cA *= a[t];
            vals[t * 128 + s] = c[t] * fmaf(cA, H, h);
        }
    }
    __syncthreads();

    // reduce y per row (warp per 2 rows) + build yi = y*silu(gate), in place
#pragma unroll
    for (int rr = 0; rr < 2; rr++) {
        int r = w * 2 + rr;
        int row = row0 + r;
        float acc = 0.f;
        float gt[4];
#pragma unroll
        for (int q = 0; q < 4; q++) {
            int s = lane + q * 32;
            acc += vals[r * 128 + s];
            gt[q] = g_gate[row * 128 + s];
        }
#pragma unroll
        for (int o = 16; o > 0; o >>= 1) acc += __shfl_xor_sync(0xffffffffu, acc, o);
#pragma unroll
        for (int q = 0; q < 4; q++) {
            int s = lane + q * 32;
            float sig = 1.0f / (1.0f + __expf(-gt[q]));
            vals[r * 128 + s] = acc * gt[q] * sig;   // yi, same rows this warp read
        }
    }
    __syncthreads();

    // GEMV + residual + warp-private LayerNorm (lane owns d=lane, lane+32)
#pragma unroll
    for (int rr = 0; rr < 2; rr++) {
        int r = w * 2 + rr;
        int row = row0 + r;
        float acc0 = 0.f, acc1 = 0.f;
#pragma unroll
        for (int i = 0; i < 128; i++) {
            float yv = vals[r * 128 + i];
            acc0 = fmaf(WT2s[i * 65 + lane],      yv, acc0);
            acc1 = fmaf(WT2s[i * 65 + lane + 32], yv, acc1);
        }
        float v0 = acc0 + x[row * 64 + lane];
        float v1 = acc1 + x[row * 64 + lane + 32];
        float sv = v0 + v1, sq = v0 * v0 + v1 * v1;
#pragma unroll
        for (int o = 16; o > 0; o >>= 1) {
            sv += __shfl_xor_sync(0xffffffffu, sv, o);
            sq += __shfl_xor_sync(0xffffffffu, sq, o);
        }
        float mu  = sv * (1.0f / 64.0f);
        float var = sq * (1.0f / 64.0f) - mu * mu;
        float inv = rsqrtf(var + 1e-5f);
        out[row * 64 + lane]      = (v0 - mu) * inv * lnw[lane]      + lnb[lane];
        out[row * 64 + lane + 32] = (v1 - mu) * inv * lnw[lane + 32] + lnb[lane + 32];
    }
}

// ---------------------------------------------------------------------------
extern "C" void kernel_launch(void* const* d_in, const int* in_sizes, int n_in,
                              void* d_out, int out_size) {
    const float* x    = (const float*)d_in[0];
    const float* Win  = (const float*)d_in[1];
    const float* Wd   = (const float*)d_in[2];
    const float* bd   = (const float*)d_in[3];
    const float* WB   = (const float*)d_in[4];
    const float* bB   = (const float*)d_in[5];
    const float* WC   = (const float*)d_in[6];
    const float* bC   = (const float*)d_in[7];
    const float* A    = (const float*)d_in[8];
    const float* Wout = (const float*)d_in[9];
    const float* lnw  = (const float*)d_in[10];
    const float* lnb  = (const float*)d_in[11];
    float* out = (float*)d_out;

    static int configured = 0;
    if (!configured) {
        cudaFuncSetAttribute(ka, cudaFuncAttributeMaxDynamicSharedMemorySize,
                             KA_SMEM_FLOATS * (int)sizeof(float));
        configured = 1;
    }

    ka<<<NROW / TC, 512, KA_SMEM_FLOATS * sizeof(float)>>>(
        x, Win, Wd, bd, WB, bB, WC, bC, A);
    kc<<<NROW / TC, 256>>>(x, Wout, lnw, lnb, out);
}

// round 4
// speedup vs baseline: 1.2752x; 1.0689x over previous
#include <cuda_runtime.h>
#include <cstdint>
#include <math.h>

// ---------------------------------------------------------------------------
// SelectiveSSM, 3-kernel pipeline. B=4, L=1024, DM=64, DS=DI=128.
//   KA: block = 16 rows = 1 chunk. Projections (16 accumulators/thread,
//       weights via L1), delta (pre-scaled by log2e) in smem only, Abar with
//       A read through L1 (no smem staging), in-block scan -> cc, ch, P, Q.
//   KB: 1 block: chunk-prefix scan of (P,Q) -> H per chunk.
//   KC: y = sum_s(ch + cc*H), silu(gate), W_out GEMV, residual, LayerNorm.
// ---------------------------------------------------------------------------

#define NB    4
#define NL    1024
#define NROW  4096
#define NCH   64
#define TC    16
#define LOG2E 1.4426950408889634f

__device__ float g_gate[NROW * 128];
__device__ float g_cc  [NROW * 128];
__device__ float g_ch  [NROW * 128];
__device__ float g_P   [NB * NCH * 128];
__device__ float g_Q   [NB * NCH * 128];
__device__ float g_H   [NB * NCH * 128];

__device__ __forceinline__ float ex2f(float v) {
    float r;
    asm("ex2.approx.ftz.f32 %0, %1;" : "=f"(r) : "f"(v));
    return r;
}

// ---------------------------------------------------------------------------
// KA: 256 blocks x 512 threads. smem ~39KB, target 2 blocks/SM.
// ---------------------------------------------------------------------------
__global__ __launch_bounds__(512) void ka(
    const float* __restrict__ x,   const float* __restrict__ Win,
    const float* __restrict__ Wd,  const float* __restrict__ bd,
    const float* __restrict__ WB,  const float* __restrict__ bB,
    const float* __restrict__ WC,  const float* __restrict__ bC,
    const float* __restrict__ A) {
    __shared__ __align__(16) float xs   [TC * 64];    // 1024
    __shared__ float dsm  [TC * 128];                 // delta * log2e
    __shared__ float bms  [TC * 128];
    __shared__ float cs   [TC * 128];
    __shared__ float abars[TC * 128];
    __shared__ float psum [8 * 64];
    __shared__ float wpool[64];
    __shared__ float pools[TC];

    int tid = threadIdx.x;
    int row0 = blockIdx.x * TC;

    // phase 0: x rows + wpool partials
    for (int i = tid; i < TC * 64; i += 512) xs[i] = x[row0 * 64 + i];
    {
        int d = tid & 63, part = tid >> 6;
        float s = 0.f;
        const float* p = Win + part * 16 * 64 + d;
#pragma unroll
        for (int i = 0; i < 16; i++) s += p[i * 64];
        psum[part * 64 + d] = s;
    }
    __syncthreads();

    // phase 1: projections. thread = feature; 16 row-accumulators.
    int mode = tid >> 7, fo = tid & 127;
    const float* wrow;
    float bias = 0.f;
    if (mode == 0)      { wrow = Win + (128 + fo) * 64; }
    else if (mode == 1) { wrow = Wd + fo * 64; bias = bd[fo]; }
    else if (mode == 2) { wrow = WB + fo * 64; bias = bB[fo]; }
    else                { wrow = WC + fo * 64; bias = bC[fo]; }

    float acc[TC];
#pragma unroll
    for (int r = 0; r < TC; r++) acc[r] = 0.f;

    const float4* w4 = (const float4*)wrow;
#pragma unroll
    for (int d4 = 0; d4 < 16; d4++) {
        float4 wv = __ldg(&w4[d4]);
#pragma unroll
        for (int r = 0; r < TC; r++) {
            float4 xv = *(const float4*)(xs + r * 64 + d4 * 4);
            acc[r] = fmaf(wv.x, xv.x, acc[r]);
            acc[r] = fmaf(wv.y, xv.y, acc[r]);
            acc[r] = fmaf(wv.z, xv.z, acc[r]);
            acc[r] = fmaf(wv.w, xv.w, acc[r]);
        }
    }

#pragma unroll
    for (int r = 0; r < TC; r++) {
        float v = acc[r] + bias;
        if (mode == 0)      g_gate[(row0 + r) * 128 + fo] = v;
        else if (mode == 1) dsm[r * 128 + fo] = log1pf(expf(v)) * LOG2E;
        else if (mode == 2) bms[r * 128 + fo] = v;
        else                cs [r * 128 + fo] = v;
    }

    // wpool (needs psum; covered by the sync below before pools are used)
    if (tid < 64) {
        float s = 0.f;
#pragma unroll
        for (int p = 0; p < 8; p++) s += psum[p * 64 + tid];
        wpool[tid] = s * (1.0f / 128.0f);
    }
    __syncthreads();

    // phase 2a: x_pool
    if (tid < TC) {
        float p = 0.f;
#pragma unroll
        for (int d = 0; d < 64; d++) p = fmaf(wpool[d], xs[tid * 64 + d], p);
        pools[tid] = p;
    }

    // phase 2b: Abar. thread (s, rq) -> 4 rows; A via L1 (reused 4x per load).
    {
        int s = tid & 127, rq = tid >> 7;
        const float* d0 = dsm + (rq * 4 + 0) * 128;
        const float* d1 = dsm + (rq * 4 + 1) * 128;
        const float* d2 = dsm + (rq * 4 + 2) * 128;
        const float* d3 = dsm + (rq * 4 + 3) * 128;
        float s0 = 0.f, s1 = 0.f, s2 = 0.f, s3 = 0.f;
#pragma unroll 8
        for (int i = 0; i < 128; i++) {
            float Av = __ldg(A + i * 128 + s);
            s0 += ex2f(d0[i] * Av);
            s1 += ex2f(d1[i] * Av);
            s2 += ex2f(d2[i] * Av);
            s3 += ex2f(d3[i] * Av);
        }
        abars[(rq * 4 + 0) * 128 + s] = s0 * (1.0f / 128.0f);
        abars[(rq * 4 + 1) * 128 + s] = s1 * (1.0f / 128.0f);
        abars[(rq * 4 + 2) * 128 + s] = s2 * (1.0f / 128.0f);
        abars[(rq * 4 + 3) * 128 + s] = s3 * (1.0f / 128.0f);
    }
    __syncthreads();

    // phase 3: in-block chunk scan -> cc, ch, P, Q
    if (tid < 128) {
        int s = tid;
        float h = 0.f, cA = 1.f;
#pragma unroll
        for (int t = 0; t < TC; t++) {
            float a = abars[t * 128 + s];
            h = fmaf(a, h, bms[t * 128 + s] * pools[t]);
            cA *= a;
            float c = cs[t * 128 + s];
            int off = (row0 + t) * 128 + s;
            g_cc[off] = c * cA;
            g_ch[off] = c * h;
        }
        int ps = blockIdx.x * 128 + s;
        g_P[ps] = cA;
        g_Q[ps] = h;
    }
}

// ---------------------------------------------------------------------------
// KB: 1 block, 512 threads: (b = tid>>7, s = tid&127), 64-chunk serial scan.
// ---------------------------------------------------------------------------
__global__ void kb() {
    int tid = threadIdx.x;
    int b = tid >> 7, s = tid & 127;
    int o0 = b * NCH * 128 + s;
    float P[2][8], Q[2][8];
#pragma unroll
    for (int j = 0; j < 8; j++) {
        P[0][j] = g_P[o0 + j * 128];
        Q[0][j] = g_Q[o0 + j * 128];
    }
    float H = 0.f;
    for (int T = 0; T < 8; T++) {
        int cur = T & 1, nxt = cur ^ 1;
        if (T < 7) {
#pragma unroll
            for (int j = 0; j < 8; j++) {
                int o = o0 + ((T + 1) * 8 + j) * 128;
                P[nxt][j] = g_P[o];
                Q[nxt][j] = g_Q[o];
            }
        }
#pragma unroll
        for (int j = 0; j < 8; j++) {
            g_H[o0 + (T * 8 + j) * 128] = H;
            H = fmaf(P[cur][j], H, Q[cur][j]);
        }
    }
}

// ---------------------------------------------------------------------------
// KC: 256 blocks x 256 threads. y = sum(ch + cc*H), silu, GEMV, LN.
// ---------------------------------------------------------------------------
__global__ __launch_bounds__(256) void kc(const float* __restrict__ x,
                                          const float* __restrict__ Wout,
                                          const float* __restrict__ lnw,
                                          const float* __restrict__ lnb,
                                          float* __restrict__ out) {
    __shared__ float WT2s[128 * 65];
    __shared__ float yis[TC * 128];
    __shared__ float Hs[128];
    int tid = threadIdx.x, lane = tid & 31, w = tid >> 5;
    int row0 = blockIdx.x * TC;

    for (int lin = tid; lin < 8192; lin += 256) {
        int d = lin >> 7, ii = lin & 127;
        WT2s[ii * 65 + d] = Wout[lin];
    }
    if (tid < 128) Hs[tid] = g_H[blockIdx.x * 128 + tid];
    __syncthreads();

    // phase A: warp per 2 rows; y reduce + yi = y*silu(gate)
#pragma unroll
    for (int rr = 0; rr < 2; rr++) {
        int r = w * 2 + rr;
        int row = row0 + r;
        float acc = 0.f;
        float gt[4];
#pragma unroll
        for (int q = 0; q < 4; q++) {
            int s = lane + q * 32;
            int off = row * 128 + s;
            acc += g_ch[off] + g_cc[off] * Hs[s];
            gt[q] = g_gate[off];
        }
#pragma unroll
        for (int o = 16; o > 0; o >>= 1) acc += __shfl_xor_sync(0xffffffffu, acc, o);
#pragma unroll
        for (int q = 0; q < 4; q++) {
            int s = lane + q * 32;
            float sig = 1.0f / (1.0f + __expf(-gt[q]));
            yis[r * 128 + s] = acc * gt[q] * sig;
        }
    }
    __syncthreads();

    // phase B: GEMV + residual + warp-private LayerNorm
#pragma unroll
    for (int rr = 0; rr < 2; rr++) {
        int r = w * 2 + rr;
        int row = row0 + r;
        float acc0 = 0.f, acc1 = 0.f;
#pragma unroll
        for (int i = 0; i < 128; i++) {
            float yv = yis[r * 128 + i];
            acc0 = fmaf(WT2s[i * 65 + lane],      yv, acc0);
            acc1 = fmaf(WT2s[i * 65 + lane + 32], yv, acc1);
        }
        float v0 = acc0 + x[row * 64 + lane];
        float v1 = acc1 + x[row * 64 + lane + 32];
        float sv = v0 + v1, sq = v0 * v0 + v1 * v1;
#pragma unroll
        for (int o = 16; o > 0; o >>= 1) {
            sv += __shfl_xor_sync(0xffffffffu, sv, o);
            sq += __shfl_xor_sync(0xffffffffu, sq, o);
        }
        float mu  = sv * (1.0f / 64.0f);
        float var = sq * (1.0f / 64.0f) - mu * mu;
        float inv = rsqrtf(var + 1e-5f);
        out[row * 64 + lane]      = (v0 - mu) * inv * lnw[lane]      + lnb[lane];
        out[row * 64 + lane + 32] = (v1 - mu) * inv * lnw[lane + 32] + lnb[lane + 32];
    }
}

// ---------------------------------------------------------------------------
extern "C" void kernel_launch(void* const* d_in, const int* in_sizes, int n_in,
                              void* d_out, int out_size) {
    const float* x    = (const float*)d_in[0];
    const float* Win  = (const float*)d_in[1];
    const float* Wd   = (const float*)d_in[2];
    const float* bd   = (const float*)d_in[3];
    const float* WB   = (const float*)d_in[4];
    const float* bB   = (const float*)d_in[5];
    const float* WC   = (const float*)d_in[6];
    const float* bC   = (const float*)d_in[7];
    const float* A    = (const float*)d_in[8];
    const float* Wout = (const float*)d_in[9];
    const float* lnw  = (const float*)d_in[10];
    const float* lnb  = (const float*)d_in[11];
    float* out = (float*)d_out;

    ka<<<NROW / TC, 512>>>(x, Win, Wd, bd, WB, bB, WC, bC, A);
    kb<<<1, 512>>>();
    kc<<<NROW / TC, 256>>>(x, Wout, lnw, lnb, out);
}